// round 9
// baseline (speedup 1.0000x reference)
#include <cuda_runtime.h>
#include <cstdint>

// AdderNet conv: out[n,co,ho,wo] = -sum_{ci,kh,kw} |x[n,ci,ho+kh-1,wo+kw-1] - w[co,ci,kh,kw]|
// N=16, C=64, H=W=56, Co=64, K=3, stride=1, pad=1 (zero pad -> padded taps contribute |w|).
//
// Packed-f32x2 core: each thread computes 2 adjacent wo for TCO co.
// The two wo share every w value, so the pair lives in one 64-bit register:
//   t   = add.rn.f32x2( (v_i, v_{i+1}), (-w, -w) )     [fma pipe, FADD2]
//   t  &= 0x7FFFFFFF7FFFFFFF                           [alu pipe, 2x LOP3]
//   acc = add.rn.f32x2( acc, t )                       [fma pipe, FADD2]
// w staged pre-negated+broadcast, padded to 4 slots/(ci,kh) -> LDS.128+LDS.64.
// Inner unit: 2 LDS + 6 FADD2 + 6 LOP3 = 14 issues / 6 terms; fma & alu pipes
// both near their 2 cyc/op floor (12 cyc each per unit), issue port at 14.
//
// x staging: static 2D walk (no div/mod), ci innermost -> 8-deep LDG batch (MLP=8).
// Grid: (7, 8, 16) = 896 blocks of 224 threads (single wave, max 7/SM).

#define BX 28
#define BY 8
#define NTHREADS (BX * BY)   // 224
#define TCO 8                // co per block
#define CI 8                 // ci chunk
#define TH 8                 // rows per block
#define TW 56                // cols per block (full width)
#define HW 56

typedef unsigned long long ull;

#define ADD2(out, a, b) \
    asm("add.rn.f32x2 %0, %1, %2;" : "=l"(out) : "l"(a), "l"(b))
#define PACK2(out, lo, hi) \
    asm("mov.b64 %0, {%1, %2};" : "=l"(out) : "f"(lo), "f"(hi))

__device__ __forceinline__ ull abs2(ull t) {
    return t & 0x7FFFFFFF7FFFFFFFULL;   // clear both sign bits (2x LOP3, alu pipe)
}

__global__ __launch_bounds__(NTHREADS)
void adder2d_kernel(const float* __restrict__ x,
                    const float* __restrict__ w,
                    float* __restrict__ out)
{
    __shared__ float xs[CI][TH + 2][TW + 2];             // 8*10*58*4 = 18.56 KB
    __shared__ __align__(16) ull ws2[TCO][CI][3][4];     // 8*8*3*4*8 = 6.0 KB, slot[3] = pad

    const int n   = blockIdx.z;
    const int co0 = blockIdx.y * TCO;
    const int h0  = blockIdx.x * TH;
    const int tx  = threadIdx.x;               // 0..27
    const int ty  = threadIdx.y;               // 0..7
    const int tid = ty * BX + tx;
    const int wo0 = tx * 2;
    const int ho  = h0 + ty;

    ull acc[TCO];
#pragma unroll
    for (int c = 0; c < TCO; c++) acc[c] = 0ULL;   // (0.f, 0.f)

    for (int ci0 = 0; ci0 < 64; ci0 += CI) {
        __syncthreads();

        // ---- stage x tile with halo (zero-filled: padding taps must see x=0) ----
        // Static 2D walk: r in {ty, ty+8}, c in {tx, tx+28, tx+56}; ci innermost
        // so the 8 guarded LDGs batch (MLP=8) and all indexing is strength-reduced.
        for (int r = ty; r < TH + 2; r += BY) {
            const int h  = h0 + r - 1;
            const bool hok = (h >= 0) & (h < HW);
            for (int c = tx; c < TW + 2; c += BX) {
                const int ww = c - 1;
                const bool ok = hok & (ww >= 0) & (ww < HW);
                const float* src = &x[((n * 64 + ci0) * HW + h) * HW + ww];
#pragma unroll
                for (int ci = 0; ci < CI; ci++) {
                    float v = 0.f;
                    if (ok) v = src[ci * HW * HW];
                    xs[ci][r][c] = v;
                }
            }
        }
        // ---- stage w slice: packed, negated, broadcast (-w,-w), padded layout ----
        {
            const int WTILE = TCO * CI * 9;              // 576
            for (int i = tid; i < WTILE; i += NTHREADS) {
                int co = i / (CI * 9);
                int r  = i - co * (CI * 9);              // ci*9 + kh*3 + kw
                int ci = r / 9;
                int t  = r - ci * 9;
                int kh = t / 3;
                int kw = t - kh * 3;
                float wv = w[((co0 + co) * 64 + ci0) * 9 + r];
                unsigned u = __float_as_uint(-wv);
                ws2[co][ci][kh][kw] = ((ull)u << 32) | (ull)u;
            }
        }
        __syncthreads();

        // ---- accumulate ----
#pragma unroll 1
        for (int ci = 0; ci < CI; ci++) {
#pragma unroll
            for (int kh = 0; kh < 3; kh++) {
                // xs row is 8B-aligned at wo0 (even) -> two LDS.64
                const float2* xrow2 = (const float2*)&xs[ci][ty + kh][wo0];
                const float2 p01 = xrow2[0];      // (v0, v1)
                const float2 p23 = xrow2[1];      // (v2, v3)
                ull v01, v12, v23;
                PACK2(v01, p01.x, p01.y);
                PACK2(v12, p01.y, p23.x);
                PACK2(v23, p23.x, p23.y);
#pragma unroll
                for (int co = 0; co < TCO; co++) {
                    // 16B-aligned pair (kw0,kw1) -> LDS.128, then LDS.64 for kw2
                    const ulonglong2 wp = *(const ulonglong2*)&ws2[co][ci][kh][0];
                    const ull w2 = ws2[co][ci][kh][2];
                    ull t0, t1, t2;
                    ADD2(t0, v01, wp.x);  t0 = abs2(t0);
                    ADD2(t1, v12, wp.y);  t1 = abs2(t1);
                    ADD2(t2, v23, w2);    t2 = abs2(t2);
                    ADD2(acc[co], acc[co], t0);
                    ADD2(acc[co], acc[co], t1);
                    ADD2(acc[co], acc[co], t2);
                }
            }
        }
    }

    // ---- write out ----
#pragma unroll
    for (int co = 0; co < TCO; co++) {
        const int o = ((n * 64 + co0 + co) * HW + ho) * HW + wo0;
        unsigned lo = (unsigned)(acc[co] & 0xFFFFFFFFULL);
        unsigned hi = (unsigned)(acc[co] >> 32);
        out[o]     = -__uint_as_float(lo);
        out[o + 1] = -__uint_as_float(hi);
    }
}

extern "C" void kernel_launch(void* const* d_in, const int* in_sizes, int n_in,
                              void* d_out, int out_size)
{
    const float* x = (const float*)d_in[0];   // [16,64,56,56]
    const float* w = (const float*)d_in[1];   // [64,64,3,3]
    float* out     = (float*)d_out;           // [16,64,56,56]

    dim3 block(BX, BY, 1);
    dim3 grid(HW / TH, 64 / TCO, 16);         // (7, 8, 16)
    adder2d_kernel<<<grid, block>>>(x, w, out);
}

// round 13
// speedup vs baseline: 1.0474x; 1.0474x over previous
#include <cuda_runtime.h>
#include <cstdint>

// AdderNet conv: out[n,co,ho,wo] = -sum_{ci,kh,kw} |x[n,ci,ho+kh-1,wo+kw-1] - w[co,ci,kh,kw]|
// N=16, C=64, H=W=56, Co=64, K=3, stride=1, pad=1.
//
// Packed-f32x2 core (2 wo per thread, 8 co per block):
//   diff = add.rn.f32x2(v_pair, (-w,-w))   [fma]
//   abs  = 64-bit AND sign-mask            [alu, 2x LOP3]
//   tree-sum 3 taps, then acc += sum       [fma]
// vs R9 (measured: 227.8us, issue 71%, no pipe saturated -> stall-bound):
//  * __launch_bounds__(224,4): reg ceiling ~72 so ptxas can pipeline across co.
//  * per ci: all 3 kh x-row pairs loaded up front (6x LDS.64, MLP=6).
//  * w repacked contiguous 9 slots/(co,ci): 4x LDS.128 + 1x LDS.64 per co
//    covering all 9 taps (5 batched loads, MLP=5; was 2-at-a-time).
//  * tree-sum shortens acc RAW chain (1 acc-add per (co,kh)).
// Grid: (7, 8, 16) = 896 blocks of 224 threads.

#define BX 28
#define BY 8
#define NTHREADS (BX * BY)   // 224
#define TCO 8                // co per block
#define CI 8                 // ci chunk
#define TH 8                 // rows per block
#define TW 56                // cols per block (full width)
#define HW 56

typedef unsigned long long ull;

#define ADD2(out, a, b) \
    asm("add.rn.f32x2 %0, %1, %2;" : "=l"(out) : "l"(a), "l"(b))
#define PACK2(out, lo, hi) \
    asm("mov.b64 %0, {%1, %2};" : "=l"(out) : "f"(lo), "f"(hi))

__device__ __forceinline__ ull abs2(ull t) {
    return t & 0x7FFFFFFF7FFFFFFFULL;   // clear both sign bits (2x LOP3, alu pipe)
}

__global__ __launch_bounds__(NTHREADS, 4)
void adder2d_kernel(const float* __restrict__ x,
                    const float* __restrict__ w,
                    float* __restrict__ out)
{
    __shared__ __align__(16) float xs[CI][TH + 2][TW + 2];  // 18.56 KB
    __shared__ __align__(16) ull   ws2[TCO][CI][12];        // 8*8*12*8 = 6 KB
    // ws2 slots 0..8 = (-w,-w) packed, t = kh*3+kw contiguous; 9..11 pad.
    // Stride 12 ull = 96 B -> every (co,ci) base is 16B-aligned.

    const int n   = blockIdx.z;
    const int co0 = blockIdx.y * TCO;
    const int h0  = blockIdx.x * TH;
    const int tx  = threadIdx.x;               // 0..27
    const int ty  = threadIdx.y;               // 0..7
    const int tid = ty * BX + tx;
    const int wo0 = tx * 2;
    const int ho  = h0 + ty;

    ull acc[TCO];
#pragma unroll
    for (int c = 0; c < TCO; c++) acc[c] = 0ULL;   // (0.f, 0.f)

    for (int ci0 = 0; ci0 < 64; ci0 += CI) {
        __syncthreads();

        // ---- stage x tile with halo (zero-filled: padding taps must see x=0) ----
        for (int r = ty; r < TH + 2; r += BY) {
            const int h  = h0 + r - 1;
            const bool hok = (h >= 0) & (h < HW);
            for (int c = tx; c < TW + 2; c += BX) {
                const int ww = c - 1;
                const bool ok = hok & (ww >= 0) & (ww < HW);
                const float* src = &x[((n * 64 + ci0) * HW + h) * HW + ww];
#pragma unroll
                for (int ci = 0; ci < CI; ci++) {
                    float v = 0.f;
                    if (ok) v = src[ci * HW * HW];
                    xs[ci][r][c] = v;
                }
            }
        }
        // ---- stage w slice: packed (-w,-w), contiguous 9 slots per (co,ci) ----
        {
            const int WTILE = TCO * CI * 9;              // 576
            for (int i = tid; i < WTILE; i += NTHREADS) {
                int co = i / (CI * 9);
                int r  = i - co * (CI * 9);              // ci*9 + t, t = kh*3+kw
                int ci = r / 9;
                int t  = r - ci * 9;
                float wv = w[((co0 + co) * 64 + ci0) * 9 + r];
                unsigned u = __float_as_uint(-wv);
                ws2[co][ci][t] = ((ull)u << 32) | (ull)u;
            }
        }
        __syncthreads();

        // ---- accumulate ----
#pragma unroll 1
        for (int ci = 0; ci < CI; ci++) {
            // Load all 3 kh rows' x pairs up front (6x LDS.64, MLP=6)
            const float2* r0 = (const float2*)&xs[ci][ty + 0][wo0];
            const float2* r1 = (const float2*)&xs[ci][ty + 1][wo0];
            const float2* r2 = (const float2*)&xs[ci][ty + 2][wo0];
            const float2 a01 = r0[0], a23 = r0[1];
            const float2 b01 = r1[0], b23 = r1[1];
            const float2 c01 = r2[0], c23 = r2[1];
            ull v01_0, v12_0, v23_0, v01_1, v12_1, v23_1, v01_2, v12_2, v23_2;
            PACK2(v01_0, a01.x, a01.y); PACK2(v12_0, a01.y, a23.x); PACK2(v23_0, a23.x, a23.y);
            PACK2(v01_1, b01.x, b01.y); PACK2(v12_1, b01.y, b23.x); PACK2(v23_1, b23.x, b23.y);
            PACK2(v01_2, c01.x, c01.y); PACK2(v12_2, c01.y, c23.x); PACK2(v23_2, c23.x, c23.y);

#pragma unroll
            for (int co = 0; co < TCO; co++) {
                // All 9 taps in 5 batched loads (4x LDS.128 + 1x LDS.64, broadcast)
                const ull* wb = ws2[co][ci];
                const ulonglong2 wA = *(const ulonglong2*)(wb + 0);  // (kh0kw0, kh0kw1)
                const ulonglong2 wB = *(const ulonglong2*)(wb + 2);  // (kh0kw2, kh1kw0)
                const ulonglong2 wC = *(const ulonglong2*)(wb + 4);  // (kh1kw1, kh1kw2)
                const ulonglong2 wD = *(const ulonglong2*)(wb + 6);  // (kh2kw0, kh2kw1)
                const ull        wE = wb[8];                         // (kh2kw2)
                ull t0, t1, t2, s;
                // kh = 0
                ADD2(t0, v01_0, wA.x); ADD2(t1, v12_0, wA.y); ADD2(t2, v23_0, wB.x);
                t0 = abs2(t0); t1 = abs2(t1); t2 = abs2(t2);
                ADD2(s, t0, t1); ADD2(s, s, t2); ADD2(acc[co], acc[co], s);
                // kh = 1
                ADD2(t0, v01_1, wB.y); ADD2(t1, v12_1, wC.x); ADD2(t2, v23_1, wC.y);
                t0 = abs2(t0); t1 = abs2(t1); t2 = abs2(t2);
                ADD2(s, t0, t1); ADD2(s, s, t2); ADD2(acc[co], acc[co], s);
                // kh = 2
                ADD2(t0, v01_2, wD.x); ADD2(t1, v12_2, wD.y); ADD2(t2, v23_2, wE);
                t0 = abs2(t0); t1 = abs2(t1); t2 = abs2(t2);
                ADD2(s, t0, t1); ADD2(s, s, t2); ADD2(acc[co], acc[co], s);
            }
        }
    }

    // ---- write out ----
#pragma unroll
    for (int co = 0; co < TCO; co++) {
        const int o = ((n * 64 + co0 + co) * HW + ho) * HW + wo0;
        unsigned lo = (unsigned)(acc[co] & 0xFFFFFFFFULL);
        unsigned hi = (unsigned)(acc[co] >> 32);
        out[o]     = -__uint_as_float(lo);
        out[o + 1] = -__uint_as_float(hi);
    }
}

extern "C" void kernel_launch(void* const* d_in, const int* in_sizes, int n_in,
                              void* d_out, int out_size)
{
    const float* x = (const float*)d_in[0];   // [16,64,56,56]
    const float* w = (const float*)d_in[1];   // [64,64,3,3]
    float* out     = (float*)d_out;           // [16,64,56,56]

    dim3 block(BX, BY, 1);
    dim3 grid(HW / TH, 64 / TCO, 16);         // (7, 8, 16)
    adder2d_kernel<<<grid, block>>>(x, w, out);
}